// round 17
// baseline (speedup 1.0000x reference)
#include <cuda_runtime.h>
#include <cuda_bf16.h>

#define N_NODES 50000
#define N_EDGES 400000
#define N_GRAPHS 64

// Scratch (device globals; no allocation allowed)
__device__ float g_buf1[N_NODES * 32];       // conv1 accumulator (pre-relu)
__device__ float g_buf2[N_NODES * 16];       // conv2 accumulator
__device__ float g_pool[N_GRAPHS * 16];      // pooled graph features
__device__ int   g_cnt[N_NODES];             // src histogram (preserved)
__device__ int   g_off[N_NODES];             // post-scatter: END offset per node
__device__ int   g_perm[N_EDGES];            // edges grouped by src

// ---------------------------------------------------------------------------
// S0: zero histogram + pool
// ---------------------------------------------------------------------------
__global__ void zero_misc(void) {
    int t = blockIdx.x * blockDim.x + threadIdx.x;
    if (t < N_NODES) g_cnt[t] = 0;
    if (t < N_GRAPHS * 16) g_pool[t] = 0.f;
}

// ---------------------------------------------------------------------------
// S1: histogram of src
// ---------------------------------------------------------------------------
__global__ void hist_kernel(const int* __restrict__ ei) {
    int e = blockIdx.x * blockDim.x + threadIdx.x;
    if (e < N_EDGES) atomicAdd(&g_cnt[__ldg(ei + e)], 1);
}

// ---------------------------------------------------------------------------
// S2: single-block exclusive scan (1024 threads, 49 nodes/thread)
// ---------------------------------------------------------------------------
__global__ void scan_kernel(void) {
    __shared__ int ssum[1024];
    const int CH = 49;                 // 1024*49 = 50176 >= N_NODES
    int t = threadIdx.x;
    int base = t * CH;
    int local[CH];
    int s = 0;
#pragma unroll
    for (int i = 0; i < CH; i++) {
        int idx = base + i;
        int v = (idx < N_NODES) ? g_cnt[idx] : 0;
        local[i] = v; s += v;
    }
    ssum[t] = s;
    __syncthreads();
    for (int d = 1; d < 1024; d <<= 1) {
        int v = (t >= d) ? ssum[t - d] : 0;
        __syncthreads();
        ssum[t] += v;
        __syncthreads();
    }
    int off = (t == 0) ? 0 : ssum[t - 1];
#pragma unroll
    for (int i = 0; i < CH; i++) {
        int idx = base + i;
        if (idx < N_NODES) g_off[idx] = off;
        off += local[i];
    }
}

// ---------------------------------------------------------------------------
// S3: scatter edge ids grouped by src (g_off becomes END offset per node)
// ---------------------------------------------------------------------------
__global__ void scatter_kernel(const int* __restrict__ ei) {
    int e = blockIdx.x * blockDim.x + threadIdx.x;
    if (e >= N_EDGES) return;
    int pos = atomicAdd(&g_off[__ldg(ei + e)], 1);
    g_perm[pos] = e;
}

// ---------------------------------------------------------------------------
// K1: agg1[n,o] = c1_bias[o] + sum_i x[n,i] * c1_root[i,o]
// ---------------------------------------------------------------------------
__global__ void node_init1(const float* __restrict__ x,
                           const float* __restrict__ root,
                           const float* __restrict__ bias) {
    int t = blockIdx.x * blockDim.x + threadIdx.x;
    if (t >= N_NODES * 32) return;
    int n = t >> 5, o = t & 31;
    const float* xr = x + n * 16;
    float acc = bias[o];
#pragma unroll
    for (int i = 0; i < 16; i++) acc = fmaf(xr[i], root[i * 32 + o], acc);
    g_buf1[t] = acc;
}

// ---------------------------------------------------------------------------
// CONV1 fused: block = 8 nodes. Phase 1: build Y rows in SMEM
// (Y[nn][k*32+o] = sum_i x[n,i]*w2[k,i*32+o]; row 32 = b2). Phase 2: warps
// stride the block's contiguous CSR edge range; per edge: h-MLP +
// shfl-contract against SMEM Y row + atomic scatter to dst.
// SMEM: 8*1056 floats Y + 256 w1 + 32 b1 = 34944 B.
// ---------------------------------------------------------------------------
__global__ __launch_bounds__(256) void conv1_kernel(
    const float* __restrict__ x, const int* __restrict__ ei,
    const float* __restrict__ ea,
    const float* __restrict__ w1, const float* __restrict__ b1,
    const float* __restrict__ w2, const float* __restrict__ b2) {
    __shared__ float sy[8 * 1056];
    __shared__ float sxn[8 * 16];
    __shared__ float s_w1[256], s_b1[32];
    int tid = threadIdx.x, lane = tid & 31, warp = tid >> 5;
    int n0 = blockIdx.x * 8;

    s_w1[tid] = w1[tid];
    if (tid < 32) s_b1[tid] = b1[tid];
    if (tid < 128) sxn[tid] = __ldg(x + (long)n0 * 16 + tid);

    // ---- phase 1: Y build (thread owns (kslot,o); 4 k's each) ----
    int o = tid & 31, kslot = tid >> 5;
    float wr[4][16];
#pragma unroll
    for (int s = 0; s < 4; s++) {
        int k = kslot + s * 8;
#pragma unroll
        for (int i = 0; i < 16; i++) wr[s][i] = __ldg(w2 + k * 512 + i * 32 + o);
    }
    float br[16];
    if (kslot == 0) {
#pragma unroll
        for (int i = 0; i < 16; i++) br[i] = __ldg(b2 + i * 32 + o);
    }
    __syncthreads();
#pragma unroll 1
    for (int nn = 0; nn < 8; nn++) {
        float acc[4] = {0.f, 0.f, 0.f, 0.f};
        float accb = 0.f;
#pragma unroll
        for (int i = 0; i < 16; i++) {
            float v = sxn[nn * 16 + i];
#pragma unroll
            for (int s = 0; s < 4; s++) acc[s] = fmaf(v, wr[s][i], acc[s]);
            if (kslot == 0) accb = fmaf(v, br[i], accb);
        }
        float* out = sy + nn * 1056;
#pragma unroll
        for (int s = 0; s < 4; s++) out[(kslot + s * 8) * 32 + o] = acc[s];
        if (kslot == 0) out[1024 + o] = accb;
    }
    __syncthreads();

    // ---- phase 2: edges of nodes n0..n0+7 (contiguous in perm) ----
    int pstart = __ldg(g_off + n0) - __ldg(g_cnt + n0);
    int pend = __ldg(g_off + n0 + 7);
    for (int p = pstart + warp; p < pend; p += 8) {
        int e = __ldg(g_perm + p);
        int src = __ldg(ei + e);
        int nn = src - n0;
        int dst = __ldg(ei + N_EDGES + e);
        const float4* ear = (const float4*)(ea + (long)e * 8);
        float4 a0 = __ldg(ear), a1 = __ldg(ear + 1);
        float h = s_b1[lane];
        h = fmaf(a0.x, s_w1[0 * 32 + lane], h);
        h = fmaf(a0.y, s_w1[1 * 32 + lane], h);
        h = fmaf(a0.z, s_w1[2 * 32 + lane], h);
        h = fmaf(a0.w, s_w1[3 * 32 + lane], h);
        h = fmaf(a1.x, s_w1[4 * 32 + lane], h);
        h = fmaf(a1.y, s_w1[5 * 32 + lane], h);
        h = fmaf(a1.z, s_w1[6 * 32 + lane], h);
        h = fmaf(a1.w, s_w1[7 * 32 + lane], h);
        h = fmaxf(h, 0.f);

        const float* yr = sy + nn * 1056;
        float msg = yr[1024 + lane];
#pragma unroll
        for (int k = 0; k < 32; k++)
            msg = fmaf(__shfl_sync(0xffffffffu, h, k), yr[k * 32 + lane], msg);
        atomicAdd(&g_buf1[(long)dst * 32 + lane], msg);
    }
}

// ---------------------------------------------------------------------------
// K4: agg2[n,o] = c2_bias[o] + sum_i relu(agg1[n,i]) * c2_root[i,o]
// ---------------------------------------------------------------------------
__global__ void node_init2(const float* __restrict__ root,
                           const float* __restrict__ bias) {
    int t = blockIdx.x * blockDim.x + threadIdx.x;
    if (t >= N_NODES * 16) return;
    int n = t >> 4, o = t & 15;
    const float* xr = g_buf1 + n * 32;
    float acc = bias[o];
#pragma unroll
    for (int i = 0; i < 32; i++) acc = fmaf(fmaxf(xr[i], 0.f), root[i * 16 + o], acc);
    g_buf2[t] = acc;
}

// ---------------------------------------------------------------------------
// CONV2 fused: block = 8 nodes. Phase 1: Y2 rows in SMEM (528 floats/node,
// built from relu(g_buf1)). Phase 2: warp takes 2 consecutive edges; each
// half-warp contracts its edge's SMEM Y row. shfls stay warp-uniform.
// SMEM: 8*528 + 8*32 + 256 + 32 = 18 KB.
// ---------------------------------------------------------------------------
__global__ __launch_bounds__(256) void conv2_kernel(
    const int* __restrict__ ei, const float* __restrict__ ea,
    const float* __restrict__ w1, const float* __restrict__ b1,
    const float* __restrict__ w2, const float* __restrict__ b2) {
    __shared__ float sy[8 * 528];
    __shared__ float sxn[8 * 32];
    __shared__ float s_w1[256], s_b1[32];
    int tid = threadIdx.x, lane = tid & 31, warp = tid >> 5;
    int n0 = blockIdx.x * 8;

    s_w1[tid] = w1[tid];
    if (tid < 32) s_b1[tid] = b1[tid];
    sxn[tid] = fmaxf(g_buf1[(long)n0 * 32 + tid], 0.f);

    // ---- phase 1: Y2 build (thread owns (kb,o); 2 k's each) ----
    int o2 = tid & 15, kb = tid >> 4;
    float wr[2][32];
#pragma unroll
    for (int s = 0; s < 2; s++) {
        int k = kb + s * 16;
#pragma unroll
        for (int i = 0; i < 32; i++) wr[s][i] = __ldg(w2 + k * 512 + i * 16 + o2);
    }
    float br[32];
    if (kb == 0) {
#pragma unroll
        for (int i = 0; i < 32; i++) br[i] = __ldg(b2 + i * 16 + o2);
    }
    __syncthreads();
#pragma unroll 1
    for (int nn = 0; nn < 8; nn++) {
        float acc0 = 0.f, acc1 = 0.f, accb = 0.f;
#pragma unroll
        for (int i = 0; i < 32; i++) {
            float v = sxn[nn * 32 + i];
            acc0 = fmaf(v, wr[0][i], acc0);
            acc1 = fmaf(v, wr[1][i], acc1);
            if (kb == 0) accb = fmaf(v, br[i], accb);
        }
        float* out = sy + nn * 528;
        out[kb * 16 + o2] = acc0;
        out[(kb + 16) * 16 + o2] = acc1;
        if (kb == 0) out[512 + o2] = accb;
    }
    __syncthreads();

    // ---- phase 2: edges; warp = 2 consecutive perm slots ----
    int pstart = __ldg(g_off + n0) - __ldg(g_cnt + n0);
    int pend = __ldg(g_off + n0 + 7);
    int sub = lane >> 4, o = lane & 15;
    for (int p0 = pstart + warp * 2; p0 < pend; p0 += 16) {
        int eA = __ldg(g_perm + p0);
        int eB = (p0 + 1 < pend) ? __ldg(g_perm + p0 + 1) : -1;

        float hA, hB = 0.f;
        {
            const float4* ear = (const float4*)(ea + (long)eA * 8);
            float4 a0 = __ldg(ear), a1 = __ldg(ear + 1);
            float h = s_b1[lane];
            h = fmaf(a0.x, s_w1[0 * 32 + lane], h);
            h = fmaf(a0.y, s_w1[1 * 32 + lane], h);
            h = fmaf(a0.z, s_w1[2 * 32 + lane], h);
            h = fmaf(a0.w, s_w1[3 * 32 + lane], h);
            h = fmaf(a1.x, s_w1[4 * 32 + lane], h);
            h = fmaf(a1.y, s_w1[5 * 32 + lane], h);
            h = fmaf(a1.z, s_w1[6 * 32 + lane], h);
            h = fmaf(a1.w, s_w1[7 * 32 + lane], h);
            hA = fmaxf(h, 0.f);
        }
        if (eB >= 0) {
            const float4* ear = (const float4*)(ea + (long)eB * 8);
            float4 a0 = __ldg(ear), a1 = __ldg(ear + 1);
            float h = s_b1[lane];
            h = fmaf(a0.x, s_w1[0 * 32 + lane], h);
            h = fmaf(a0.y, s_w1[1 * 32 + lane], h);
            h = fmaf(a0.z, s_w1[2 * 32 + lane], h);
            h = fmaf(a0.w, s_w1[3 * 32 + lane], h);
            h = fmaf(a1.x, s_w1[4 * 32 + lane], h);
            h = fmaf(a1.y, s_w1[5 * 32 + lane], h);
            h = fmaf(a1.z, s_w1[6 * 32 + lane], h);
            h = fmaf(a1.w, s_w1[7 * 32 + lane], h);
            hB = fmaxf(h, 0.f);
        }

        int eM = sub ? eB : eA;
        int nnM = (eM >= 0) ? (__ldg(ei + eM) - n0) : 0;
        const float* yr = sy + nnM * 528;
        float msg = yr[512 + o];
#pragma unroll
        for (int k = 0; k < 32; k++) {
            float ha = __shfl_sync(0xffffffffu, hA, k);
            float hb = __shfl_sync(0xffffffffu, hB, k);
            msg = fmaf(sub ? hb : ha, yr[k * 16 + o], msg);
        }
        if (eM >= 0) {
            int dst = __ldg(ei + N_EDGES + eM);
            atomicAdd(&g_buf2[(long)dst * 16 + o], msg);
        }
    }
}

// ---------------------------------------------------------------------------
// K6: relu(agg2) + global_add_pool via per-block shared accumulation
// ---------------------------------------------------------------------------
__global__ void pool_kernel(const int* __restrict__ batch) {
    __shared__ float sg[N_GRAPHS * 16];
    int tid = threadIdx.x;
    for (int i = tid; i < N_GRAPHS * 16; i += blockDim.x) sg[i] = 0.f;
    __syncthreads();
    int t = blockIdx.x * blockDim.x + tid;
    int stride = gridDim.x * blockDim.x;
    for (int n = t; n < N_NODES; n += stride) {
        int b = batch[n];
        const float* r = g_buf2 + n * 16;
#pragma unroll
        for (int f = 0; f < 16; f++)
            atomicAdd(&sg[b * 16 + f], fmaxf(r[f], 0.f));
    }
    __syncthreads();
    for (int i = tid; i < N_GRAPHS * 16; i += blockDim.x)
        if (sg[i] != 0.f) atomicAdd(&g_pool[i], sg[i]);
}

// ---------------------------------------------------------------------------
// K7: head — per-graph MLP
// ---------------------------------------------------------------------------
__global__ void head_kernel(const float* __restrict__ fc1_w,
                            const float* __restrict__ fc1_b,
                            const float* __restrict__ out_w,
                            const float* __restrict__ out_b,
                            float* __restrict__ out) {
    int t = threadIdx.x;
    if (t >= N_GRAPHS) return;
    const float* gr = g_pool + t * 16;
    float r = out_b[0];
#pragma unroll
    for (int o = 0; o < 32; o++) {
        float acc = fc1_b[o];
#pragma unroll
        for (int i = 0; i < 16; i++) acc = fmaf(gr[i], fc1_w[i * 32 + o], acc);
        r = fmaf(fmaxf(acc, 0.f), out_w[o], r);
    }
    out[t] = r;
}

// ---------------------------------------------------------------------------
extern "C" void kernel_launch(void* const* d_in, const int* in_sizes, int n_in,
                              void* d_out, int out_size) {
    const float* x        = (const float*)d_in[0];
    const int*   ei       = (const int*)  d_in[1];
    const float* ea       = (const float*)d_in[2];
    const int*   batch    = (const int*)  d_in[3];
    const float* c1_w1    = (const float*)d_in[4];
    const float* c1_b1    = (const float*)d_in[5];
    const float* c1_w2    = (const float*)d_in[6];
    const float* c1_b2    = (const float*)d_in[7];
    const float* c1_root  = (const float*)d_in[8];
    const float* c1_bias  = (const float*)d_in[9];
    const float* c2_w1    = (const float*)d_in[10];
    const float* c2_b1    = (const float*)d_in[11];
    const float* c2_w2    = (const float*)d_in[12];
    const float* c2_b2    = (const float*)d_in[13];
    const float* c2_root  = (const float*)d_in[14];
    const float* c2_bias  = (const float*)d_in[15];
    const float* fc1_w    = (const float*)d_in[16];
    const float* fc1_b    = (const float*)d_in[17];
    const float* out_w    = (const float*)d_in[18];
    const float* out_b    = (const float*)d_in[19];
    float* out = (float*)d_out;

    // CSR build (perm + counts reused by both convs)
    zero_misc<<<(N_NODES + 255) / 256, 256>>>();
    hist_kernel<<<(N_EDGES + 255) / 256, 256>>>(ei);
    scan_kernel<<<1, 1024>>>();
    scatter_kernel<<<(N_EDGES + 255) / 256, 256>>>(ei);

    // conv1 (Y built in SMEM inside conv1_kernel)
    node_init1<<<(N_NODES * 32 + 255) / 256, 256>>>(x, c1_root, c1_bias);
    conv1_kernel<<<N_NODES / 8, 256>>>(x, ei, ea, c1_w1, c1_b1, c1_w2, c1_b2);
    // conv2 (relu fused into consumers of g_buf1)
    node_init2<<<(N_NODES * 16 + 255) / 256, 256>>>(c2_root, c2_bias);
    conv2_kernel<<<N_NODES / 8, 256>>>(ei, ea, c2_w1, c2_b1, c2_w2, c2_b2);
    // pool + head
    pool_kernel<<<120, 256>>>(batch);
    head_kernel<<<1, 64>>>(fc1_w, fc1_b, out_w, out_b, out);
}